// round 1
// baseline (speedup 1.0000x reference)
#include <cuda_runtime.h>

// Problem constants
#define BATCH    2
#define SEQ      8192
#define DM       768
#define NH       12
#define HD       64
#define CHUNKLEN 512
#define NLM      32
#define NCH      16           // SEQ / CHUNKLEN
#define LK       544          // NLM + CHUNKLEN
#define KVROWS   (BATCH*NCH*LK)   // 17408
#define QROWS    (BATCH*SEQ)      // 16384

// Scratch (device globals: the sanctioned alloc-free workaround)
__device__ float g_lm[BATCH*NLM*DM];
__device__ float g_kvin[(size_t)KVROWS*DM];
__device__ float g_q[(size_t)QROWS*DM];
__device__ float g_k[(size_t)KVROWS*DM];
__device__ float g_v[(size_t)KVROWS*DM];
__device__ float g_ctx[(size_t)QROWS*DM];

// ---------------------------------------------------------------------------
// 1. Landmarks: mean-pool 32 segments of 256 tokens. One block per (b, l),
//    768 threads = one per feature dim; reads coalesced across d.
// ---------------------------------------------------------------------------
__global__ void landmark_kernel(const float* __restrict__ x) {
    int b = blockIdx.x >> 5, l = blockIdx.x & 31, d = threadIdx.x;
    const float* p = x + ((size_t)(b*SEQ + l*256))*DM + d;
    float s = 0.f;
    #pragma unroll 8
    for (int t = 0; t < 256; t++) s += p[(size_t)t*DM];
    g_lm[(b*NLM + l)*DM + d] = s * (1.f/256.f);
}

// ---------------------------------------------------------------------------
// 2. Gather [landmarks ++ chunk tokens] into one dense (17408, 768) matrix so
//    the K and V projections are plain GEMMs sharing one input.
// ---------------------------------------------------------------------------
__global__ void gather_kv_kernel(const float* __restrict__ x) {
    int idx = blockIdx.x*blockDim.x + threadIdx.x;   // float4 index
    int row = idx / 192, c = idx - row*192;          // 192 float4 per row
    int b   = row / (NCH*LK);
    int rem = row - b*(NCH*LK);
    int ch  = rem / LK;
    int t   = rem - ch*LK;
    float4 v;
    if (t < NLM)
        v = ((const float4*)g_lm)[(size_t)(b*NLM + t)*192 + c];
    else
        v = ((const float4*)x)[((size_t)b*SEQ + (size_t)ch*CHUNKLEN + (t-NLM))*192 + c];
    ((float4*)g_kvin)[(size_t)row*192 + c] = v;
}

// ---------------------------------------------------------------------------
// 3. SGEMM (NT): C[m,n] = bias[n] + sum_k A[m,k] * W[n,k],  K = N = 768.
//    128x128 block tile, BK=16, 256 threads, 8x8 per thread (4+64 split for
//    conflict-free 128-bit shared loads). M and N exactly tiled by the grid.
// ---------------------------------------------------------------------------
__global__ __launch_bounds__(256) void sgemm_nt_bias(
    const float* __restrict__ A, const float* __restrict__ W,
    const float* __restrict__ bias, float* __restrict__ C)
{
    __shared__ float As[16][132];   // padded stride (528B, 16B-aligned)
    __shared__ float Bs[16][132];
    const int t  = threadIdx.x;
    const int m0 = blockIdx.y * 128, n0 = blockIdx.x * 128;
    const int tx = t & 15, ty = t >> 4;
    const int lr = t >> 2, lc = (t & 3) << 2;

    float acc[8][8];
    #pragma unroll
    for (int i = 0; i < 8; i++)
        #pragma unroll
        for (int j = 0; j < 8; j++) acc[i][j] = 0.f;

    for (int k0 = 0; k0 < DM; k0 += 16) {
        #pragma unroll
        for (int i = 0; i < 2; i++) {
            int r = lr + i*64;
            float4 va = *(const float4*)(A + (size_t)(m0+r)*DM + k0 + lc);
            As[lc+0][r]=va.x; As[lc+1][r]=va.y; As[lc+2][r]=va.z; As[lc+3][r]=va.w;
            float4 vb = *(const float4*)(W + (size_t)(n0+r)*DM + k0 + lc);
            Bs[lc+0][r]=vb.x; Bs[lc+1][r]=vb.y; Bs[lc+2][r]=vb.z; Bs[lc+3][r]=vb.w;
        }
        __syncthreads();
        #pragma unroll
        for (int k = 0; k < 16; k++) {
            float a[8], b[8];
            *(float4*)(a)   = *(const float4*)&As[k][ty*4];
            *(float4*)(a+4) = *(const float4*)&As[k][ty*4+64];
            *(float4*)(b)   = *(const float4*)&Bs[k][tx*4];
            *(float4*)(b+4) = *(const float4*)&Bs[k][tx*4+64];
            #pragma unroll
            for (int i = 0; i < 8; i++)
                #pragma unroll
                for (int j = 0; j < 8; j++) acc[i][j] += a[i]*b[j];
        }
        __syncthreads();
    }

    float4 bv0 = *(const float4*)(bias + n0 + tx*4);
    float4 bv1 = *(const float4*)(bias + n0 + tx*4 + 64);
    #pragma unroll
    for (int i = 0; i < 8; i++) {
        int m = m0 + ty*4 + (i < 4 ? i : 60 + i);   // i=4..7 -> +64..67
        float4 o0, o1;
        o0.x = acc[i][0]+bv0.x; o0.y = acc[i][1]+bv0.y;
        o0.z = acc[i][2]+bv0.z; o0.w = acc[i][3]+bv0.w;
        o1.x = acc[i][4]+bv1.x; o1.y = acc[i][5]+bv1.y;
        o1.z = acc[i][6]+bv1.z; o1.w = acc[i][7]+bv1.w;
        *(float4*)(C + (size_t)m*DM + n0 + tx*4)      = o0;
        *(float4*)(C + (size_t)m*DM + n0 + tx*4 + 64) = o1;
    }
}

// ---------------------------------------------------------------------------
// 4. Attention: grid (qtile=4, head=12, b*chunk=32), 128 threads, one query
//    per thread. K/V streamed through smem in 32-row tiles (544 = 17*32).
//    Flash-style online softmax, one acc rescale per tile.
// ---------------------------------------------------------------------------
__global__ __launch_bounds__(128) void attn_kernel() {
    const int qt = blockIdx.x, h = blockIdx.y, bc = blockIdx.z;
    const int tid = threadIdx.x;
    __shared__ float Ks[32][64];
    __shared__ float Vs[32][64];

    const int token = bc*CHUNKLEN + qt*128 + tid;
    const float* qp = g_q + (size_t)token*DM + h*HD;
    float qr[64];
    #pragma unroll
    for (int j = 0; j < 16; j++) {
        float4 v = *(const float4*)(qp + 4*j);
        qr[4*j]=v.x; qr[4*j+1]=v.y; qr[4*j+2]=v.z; qr[4*j+3]=v.w;
    }

    float acc[64];
    #pragma unroll
    for (int j = 0; j < 64; j++) acc[j] = 0.f;
    float m = -1e30f, l = 0.f;
    const size_t kbase = (size_t)bc*LK;

    for (int k0 = 0; k0 < LK; k0 += 32) {
        #pragma unroll
        for (int i = 0; i < 4; i++) {
            int j = tid + 128*i;                    // 0..511 float4 of the tile
            int r = j >> 4, c = (j & 15) << 2;
            *(float4*)&Ks[r][c] = *(const float4*)(g_k + (kbase + k0 + r)*DM + h*HD + c);
            *(float4*)&Vs[r][c] = *(const float4*)(g_v + (kbase + k0 + r)*DM + h*HD + c);
        }
        __syncthreads();

        float s[32];
        #pragma unroll 4
        for (int r = 0; r < 32; r++) {
            const float4* kp = (const float4*)Ks[r];
            float a0=0.f, a1=0.f, a2=0.f, a3=0.f;
            #pragma unroll
            for (int j = 0; j < 16; j++) {
                float4 kv = kp[j];
                a0 += qr[4*j  ]*kv.x; a1 += qr[4*j+1]*kv.y;
                a2 += qr[4*j+2]*kv.z; a3 += qr[4*j+3]*kv.w;
            }
            s[r] = (a0+a1+a2+a3) * 0.125f;          // hd^-0.5 = 1/8
        }

        float tmax = s[0];
        #pragma unroll
        for (int r = 1; r < 32; r++) tmax = fmaxf(tmax, s[r]);
        float mnew = fmaxf(m, tmax);
        float corr = __expf(m - mnew);
        l *= corr;
        #pragma unroll
        for (int j = 0; j < 64; j++) acc[j] *= corr;

        #pragma unroll 2
        for (int r = 0; r < 32; r++) {
            float p = __expf(s[r] - mnew);
            l += p;
            const float4* vp = (const float4*)Vs[r];
            #pragma unroll
            for (int j = 0; j < 16; j++) {
                float4 vv = vp[j];
                acc[4*j  ] += p*vv.x; acc[4*j+1] += p*vv.y;
                acc[4*j+2] += p*vv.z; acc[4*j+3] += p*vv.w;
            }
        }
        m = mnew;
        __syncthreads();
    }

    float inv = 1.f / l;
    float* op = g_ctx + (size_t)token*DM + h*HD;
    #pragma unroll
    for (int j = 0; j < 16; j++) {
        float4 v;
        v.x=acc[4*j]*inv; v.y=acc[4*j+1]*inv; v.z=acc[4*j+2]*inv; v.w=acc[4*j+3]*inv;
        *(float4*)(op + 4*j) = v;
    }
}

// ---------------------------------------------------------------------------
// Launch. All kernels on the (per-thread) default stream: sequential deps,
// graph-capturable, no allocations, no syncs.
// ---------------------------------------------------------------------------
extern "C" void kernel_launch(void* const* d_in, const int* in_sizes, int n_in,
                              void* d_out, int out_size)
{
    const float* x  = (const float*)d_in[0];
    const float* Wq = (const float*)d_in[1];
    const float* bq = (const float*)d_in[2];
    const float* Wk = (const float*)d_in[3];
    const float* bk = (const float*)d_in[4];
    const float* Wv = (const float*)d_in[5];
    const float* bv = (const float*)d_in[6];
    const float* Wo = (const float*)d_in[7];
    const float* bo = (const float*)d_in[8];
    float* out = (float*)d_out;

    float *p_kvin, *p_q, *p_k, *p_v, *p_ctx;
    cudaGetSymbolAddress((void**)&p_kvin, g_kvin);
    cudaGetSymbolAddress((void**)&p_q,    g_q);
    cudaGetSymbolAddress((void**)&p_k,    g_k);
    cudaGetSymbolAddress((void**)&p_v,    g_v);
    cudaGetSymbolAddress((void**)&p_ctx,  g_ctx);

    landmark_kernel<<<BATCH*NLM, DM>>>(x);
    gather_kv_kernel<<<(KVROWS*192)/256, 256>>>(x);                 // 13056 blocks exact
    sgemm_nt_bias<<<dim3(6, QROWS/128),  256>>>(x,      Wq, bq, p_q);
    sgemm_nt_bias<<<dim3(6, KVROWS/128), 256>>>(p_kvin, Wk, bk, p_k);
    sgemm_nt_bias<<<dim3(6, KVROWS/128), 256>>>(p_kvin, Wv, bv, p_v);
    attn_kernel<<<dim3(4, NH, BATCH*NCH), 128>>>();
    sgemm_nt_bias<<<dim3(6, QROWS/128),  256>>>(p_ctx,  Wo, bo, out);
}

// round 3
// speedup vs baseline: 3.3638x; 3.3638x over previous
#include <cuda_runtime.h>
#include <cstdint>

// Problem constants
#define BATCH    2
#define SEQ      8192
#define DM       768
#define NH       12
#define HD       64
#define CHUNKLEN 512
#define NLM      32
#define NCH      16           // SEQ / CHUNKLEN
#define LK       544          // NLM + CHUNKLEN
#define KVROWS   (BATCH*NCH*LK)   // 17408
#define QROWS    (BATCH*SEQ)      // 16384

// Scratch (device globals: the sanctioned alloc-free workaround)
__device__ float g_lm[BATCH*NLM*DM];
__device__ float g_kvin[(size_t)KVROWS*DM];
__device__ float g_q[(size_t)QROWS*DM];
__device__ float g_k[(size_t)KVROWS*DM];
__device__ float g_v[(size_t)KVROWS*DM];
__device__ float g_ctx[(size_t)QROWS*DM];

__device__ __forceinline__ uint32_t f2tf32(float f) {
    uint32_t u;
    asm("cvt.rna.tf32.f32 %0, %1;" : "=r"(u) : "f"(f));
    return u;
}

__device__ __forceinline__ void mma_tf32(float c[4], const uint32_t a[4], const uint32_t b[2]) {
    asm volatile(
        "mma.sync.aligned.m16n8k8.row.col.f32.tf32.tf32.f32 "
        "{%0,%1,%2,%3}, {%4,%5,%6,%7}, {%8,%9}, {%0,%1,%2,%3};\n"
        : "+f"(c[0]), "+f"(c[1]), "+f"(c[2]), "+f"(c[3])
        : "r"(a[0]), "r"(a[1]), "r"(a[2]), "r"(a[3]), "r"(b[0]), "r"(b[1]));
}

// ---------------------------------------------------------------------------
// 1. Landmarks: mean-pool 32 segments of 256 tokens.
// ---------------------------------------------------------------------------
__global__ void landmark_kernel(const float* __restrict__ x) {
    int b = blockIdx.x >> 5, l = blockIdx.x & 31, d = threadIdx.x;
    const float* p = x + ((size_t)(b*SEQ + l*256))*DM + d;
    float s = 0.f;
    #pragma unroll 8
    for (int t = 0; t < 256; t++) s += p[(size_t)t*DM];
    g_lm[(b*NLM + l)*DM + d] = s * (1.f/256.f);
}

// ---------------------------------------------------------------------------
// 2. Gather [landmarks ++ chunk tokens] into one dense (17408, 768) matrix.
// ---------------------------------------------------------------------------
__global__ void gather_kv_kernel(const float* __restrict__ x) {
    int idx = blockIdx.x*blockDim.x + threadIdx.x;   // float4 index
    int row = idx / 192, c = idx - row*192;
    int b   = row / (NCH*LK);
    int rem = row - b*(NCH*LK);
    int ch  = rem / LK;
    int t   = rem - ch*LK;
    float4 v;
    if (t < NLM)
        v = ((const float4*)g_lm)[(size_t)(b*NLM + t)*192 + c];
    else
        v = ((const float4*)x)[((size_t)b*SEQ + (size_t)ch*CHUNKLEN + (t-NLM))*192 + c];
    ((float4*)g_kvin)[(size_t)row*192 + c] = v;
}

// ---------------------------------------------------------------------------
// 3. tf32 tensor-core GEMM (NT): C[m,n] = bias[n] + sum_k A[m,k] * W[n,k]
//    128x128 tile, BK=32, 256 threads, 8 warps (2x4), 64x32/warp m16n8k8.
// ---------------------------------------------------------------------------
#define BM 128
#define BN 128
#define BK 32
#define KSTR 36   // BK + 4 pad; 36 mod 32 = 4 -> conflict-free frag loads

__global__ __launch_bounds__(256) void gemm_tf32(
    const float* __restrict__ A, const float* __restrict__ W,
    const float* __restrict__ bias, float* __restrict__ C)
{
    __shared__ uint32_t As[BM][KSTR];
    __shared__ uint32_t Ws[BN][KSTR];
    const int t    = threadIdx.x;
    const int lane = t & 31, warp = t >> 5;
    const int wm   = warp >> 2, wn = warp & 3;
    const int m0   = blockIdx.y * BM, n0 = blockIdx.x * BN;
    const int lr   = t >> 3;
    const int lc   = (t & 7) << 2;
    const int gid  = lane >> 2;
    const int tig  = lane & 3;

    float c[4][4][4];
    #pragma unroll
    for (int mi = 0; mi < 4; mi++)
        #pragma unroll
        for (int ni = 0; ni < 4; ni++)
            #pragma unroll
            for (int r = 0; r < 4; r++) c[mi][ni][r] = 0.f;

    const float* Ag = A + (size_t)(m0 + lr) * DM + lc;
    const float* Wg = W + (size_t)(n0 + lr) * DM + lc;

    float4 pa[4], pw[4];
    #pragma unroll
    for (int i = 0; i < 4; i++) {
        pa[i] = *(const float4*)(Ag + (size_t)i*32*DM);
        pw[i] = *(const float4*)(Wg + (size_t)i*32*DM);
    }

    for (int kt = 0; kt < DM/BK; kt++) {
        #pragma unroll
        for (int i = 0; i < 4; i++) {
            uint32_t* ps = &As[lr + 32*i][lc];
            ps[0]=f2tf32(pa[i].x); ps[1]=f2tf32(pa[i].y);
            ps[2]=f2tf32(pa[i].z); ps[3]=f2tf32(pa[i].w);
            uint32_t* qs = &Ws[lr + 32*i][lc];
            qs[0]=f2tf32(pw[i].x); qs[1]=f2tf32(pw[i].y);
            qs[2]=f2tf32(pw[i].z); qs[3]=f2tf32(pw[i].w);
        }
        __syncthreads();

        if (kt < DM/BK - 1) {
            int off = (kt + 1) * BK;
            #pragma unroll
            for (int i = 0; i < 4; i++) {
                pa[i] = *(const float4*)(Ag + (size_t)i*32*DM + off);
                pw[i] = *(const float4*)(Wg + (size_t)i*32*DM + off);
            }
        }

        #pragma unroll
        for (int kk = 0; kk < 4; kk++) {
            const int k = kk*8 + tig;
            uint32_t a[4][4], b[4][2];
            #pragma unroll
            for (int mi = 0; mi < 4; mi++) {
                int r = wm*64 + mi*16 + gid;
                a[mi][0] = As[r    ][k    ];
                a[mi][1] = As[r + 8][k    ];
                a[mi][2] = As[r    ][k + 4];
                a[mi][3] = As[r + 8][k + 4];
            }
            #pragma unroll
            for (int ni = 0; ni < 4; ni++) {
                int n = wn*32 + ni*8 + gid;
                b[ni][0] = Ws[n][k    ];
                b[ni][1] = Ws[n][k + 4];
            }
            #pragma unroll
            for (int mi = 0; mi < 4; mi++)
                #pragma unroll
                for (int ni = 0; ni < 4; ni++)
                    mma_tf32(c[mi][ni], a[mi], b[ni]);
        }
        __syncthreads();
    }

    #pragma unroll
    for (int mi = 0; mi < 4; mi++) {
        int r0 = m0 + wm*64 + mi*16 + gid;
        #pragma unroll
        for (int ni = 0; ni < 4; ni++) {
            int col = n0 + wn*32 + ni*8 + (tig << 1);
            float2 bv = *(const float2*)(bias + col);
            float2 o0, o1;
            o0.x = c[mi][ni][0] + bv.x; o0.y = c[mi][ni][1] + bv.y;
            o1.x = c[mi][ni][2] + bv.x; o1.y = c[mi][ni][3] + bv.y;
            *(float2*)(C + (size_t)r0*DM + col)       = o0;
            *(float2*)(C + (size_t)(r0+8)*DM + col)   = o1;
        }
    }
}

// ---------------------------------------------------------------------------
// 4. Tensor-core flash attention. Block = (qtile of 128, head, b*chunk).
//    8 warps x 16 q-rows each. KV streamed in 32-row tiles (17 tiles).
//    QK^T and P*V both via tf32 mma.m16n8k8; softmax in fp32 registers.
//    Smem strides: Ks 68 (=4 mod 32), Vs 72 (=8 mod 32), Ps 36 (=4 mod 32)
//    -> all fragment loads conflict-free. Ps is per-warp-private (rows
//    wm*16..wm*16+15), so only __syncwarp() guards it.
// ---------------------------------------------------------------------------
#define KSTRA 68
#define VSTRA 72
#define PSTRA 36

__global__ __launch_bounds__(256) void attn_kernel() {
    __shared__ uint32_t Ks[32][KSTRA];
    __shared__ uint32_t Vs[32][VSTRA];
    __shared__ uint32_t Ps[128][PSTRA];

    const int qt = blockIdx.x, h = blockIdx.y, bc = blockIdx.z;
    const int tid  = threadIdx.x;
    const int lane = tid & 31, warp = tid >> 5;   // warp = wm (8 warps, 16 rows each)
    const int gid  = lane >> 2, tig = lane & 3;

    const int qrow0 = bc*CHUNKLEN + qt*128 + warp*16 + gid;  // + 8 for second row
    const size_t kbase = (size_t)bc * LK;

    // Q fragments: 8 k-steps of hd, kept in registers for all tiles
    uint32_t qa[8][4];
    {
        const float* qp = g_q + (size_t)qrow0*DM + h*HD;
        #pragma unroll
        for (int ks = 0; ks < 8; ks++) {
            qa[ks][0] = f2tf32(qp[ks*8 + tig]);
            qa[ks][1] = f2tf32(qp[(size_t)8*DM + ks*8 + tig]);
            qa[ks][2] = f2tf32(qp[ks*8 + tig + 4]);
            qa[ks][3] = f2tf32(qp[(size_t)8*DM + ks*8 + tig + 4]);
        }
    }

    float o[8][4];
    #pragma unroll
    for (int ni = 0; ni < 8; ni++)
        #pragma unroll
        for (int j = 0; j < 4; j++) o[ni][j] = 0.f;
    float m0r = -1e30f, m1r = -1e30f;   // running row maxima (rows gid, gid+8)
    float l0 = 0.f, l1 = 0.f;           // per-thread partial row sums

    for (int k0 = 0; k0 < LK; k0 += 32) {
        // ---- stage K and V tiles (tf32, float4-aligned vector stores) ----
        #pragma unroll
        for (int i = 0; i < 2; i++) {
            int idx = tid + 256*i;            // 512 float4 of the 32x64 tile
            int r = idx >> 4, c4 = (idx & 15) << 2;
            const size_t rowoff = (kbase + k0 + r)*DM + h*HD + c4;
            float4 kv4 = *(const float4*)(g_k + rowoff);
            uint4 kt4 = { f2tf32(kv4.x), f2tf32(kv4.y), f2tf32(kv4.z), f2tf32(kv4.w) };
            *(uint4*)&Ks[r][c4] = kt4;
            float4 vv4 = *(const float4*)(g_v + rowoff);
            uint4 vt4 = { f2tf32(vv4.x), f2tf32(vv4.y), f2tf32(vv4.z), f2tf32(vv4.w) };
            *(uint4*)&Vs[r][c4] = vt4;
        }
        __syncthreads();

        // ---- S = Q K^T * scale : warp computes 16x32 via 4 n-atoms x 8 k ----
        float s[4][4];
        #pragma unroll
        for (int ni = 0; ni < 4; ni++)
            #pragma unroll
            for (int j = 0; j < 4; j++) s[ni][j] = 0.f;
        #pragma unroll
        for (int ks = 0; ks < 8; ks++) {
            const int k = ks*8 + tig;
            uint32_t b[4][2];
            #pragma unroll
            for (int ni = 0; ni < 4; ni++) {
                int n = ni*8 + gid;
                b[ni][0] = Ks[n][k];
                b[ni][1] = Ks[n][k + 4];
            }
            #pragma unroll
            for (int ni = 0; ni < 4; ni++)
                mma_tf32(s[ni], qa[ks], b[ni]);
        }
        #pragma unroll
        for (int ni = 0; ni < 4; ni++)
            #pragma unroll
            for (int j = 0; j < 4; j++) s[ni][j] *= 0.125f;

        // ---- online softmax update ----
        float tm0 = s[0][0], tm1 = s[0][2];
        #pragma unroll
        for (int ni = 0; ni < 4; ni++) {
            tm0 = fmaxf(tm0, fmaxf(s[ni][0], s[ni][1]));
            tm1 = fmaxf(tm1, fmaxf(s[ni][2], s[ni][3]));
        }
        tm0 = fmaxf(tm0, __shfl_xor_sync(0xffffffffu, tm0, 1));
        tm0 = fmaxf(tm0, __shfl_xor_sync(0xffffffffu, tm0, 2));
        tm1 = fmaxf(tm1, __shfl_xor_sync(0xffffffffu, tm1, 1));
        tm1 = fmaxf(tm1, __shfl_xor_sync(0xffffffffu, tm1, 2));
        float mn0 = fmaxf(m0r, tm0), mn1 = fmaxf(m1r, tm1);
        float cr0 = __expf(m0r - mn0), cr1 = __expf(m1r - mn1);
        m0r = mn0; m1r = mn1;
        l0 *= cr0; l1 *= cr1;
        #pragma unroll
        for (int ni = 0; ni < 8; ni++) {
            o[ni][0] *= cr0; o[ni][1] *= cr0;
            o[ni][2] *= cr1; o[ni][3] *= cr1;
        }

        // ---- P = exp(S - m); write to per-warp Ps patch as tf32 ----
        const int pr0 = warp*16 + gid;
        #pragma unroll
        for (int ni = 0; ni < 4; ni++) {
            float p00 = __expf(s[ni][0] - mn0);
            float p01 = __expf(s[ni][1] - mn0);
            float p10 = __expf(s[ni][2] - mn1);
            float p11 = __expf(s[ni][3] - mn1);
            l0 += p00 + p01;
            l1 += p10 + p11;
            int col = ni*8 + (tig << 1);
            Ps[pr0    ][col]   = f2tf32(p00);
            Ps[pr0    ][col+1] = f2tf32(p01);
            Ps[pr0 + 8][col]   = f2tf32(p10);
            Ps[pr0 + 8][col+1] = f2tf32(p11);
        }
        __syncwarp();

        // ---- O += P V : 4 k-atoms (kv) x 8 n-atoms (hd) ----
        #pragma unroll
        for (int ka = 0; ka < 4; ka++) {
            uint32_t a[4];
            a[0] = Ps[pr0    ][ka*8 + tig];
            a[1] = Ps[pr0 + 8][ka*8 + tig];
            a[2] = Ps[pr0    ][ka*8 + tig + 4];
            a[3] = Ps[pr0 + 8][ka*8 + tig + 4];
            #pragma unroll
            for (int ni = 0; ni < 8; ni++) {
                uint32_t b[2];
                b[0] = Vs[ka*8 + tig    ][ni*8 + gid];
                b[1] = Vs[ka*8 + tig + 4][ni*8 + gid];
                mma_tf32(o[ni], a, b);
            }
        }
        __syncwarp();
        __syncthreads();   // all warps done with Ks/Vs before restage
    }

    // ---- finalize: reduce l across quad, normalize, store ----
    l0 += __shfl_xor_sync(0xffffffffu, l0, 1);
    l0 += __shfl_xor_sync(0xffffffffu, l0, 2);
    l1 += __shfl_xor_sync(0xffffffffu, l1, 1);
    l1 += __shfl_xor_sync(0xffffffffu, l1, 2);
    float inv0 = 1.f / l0, inv1 = 1.f / l1;

    float* op = g_ctx + (size_t)qrow0*DM + h*HD;
    #pragma unroll
    for (int ni = 0; ni < 8; ni++) {
        int col = ni*8 + (tig << 1);
        float2 w0 = { o[ni][0]*inv0, o[ni][1]*inv0 };
        float2 w1 = { o[ni][2]*inv1, o[ni][3]*inv1 };
        *(float2*)(op + col)               = w0;
        *(float2*)(op + (size_t)8*DM + col) = w1;
    }
}

// ---------------------------------------------------------------------------
// Launch
// ---------------------------------------------------------------------------
extern "C" void kernel_launch(void* const* d_in, const int* in_sizes, int n_in,
                              void* d_out, int out_size)
{
    const float* x  = (const float*)d_in[0];
    const float* Wq = (const float*)d_in[1];
    const float* bq = (const float*)d_in[2];
    const float* Wk = (const float*)d_in[3];
    const float* bk = (const float*)d_in[4];
    const float* Wv = (const float*)d_in[5];
    const float* bv = (const float*)d_in[6];
    const float* Wo = (const float*)d_in[7];
    const float* bo = (const float*)d_in[8];
    float* out = (float*)d_out;

    float *p_kvin, *p_q, *p_k, *p_v, *p_ctx;
    cudaGetSymbolAddress((void**)&p_kvin, g_kvin);
    cudaGetSymbolAddress((void**)&p_q,    g_q);
    cudaGetSymbolAddress((void**)&p_k,    g_k);
    cudaGetSymbolAddress((void**)&p_v,    g_v);
    cudaGetSymbolAddress((void**)&p_ctx,  g_ctx);

    landmark_kernel<<<BATCH*NLM, DM>>>(x);
    gather_kv_kernel<<<(KVROWS*192)/256, 256>>>(x);
    gemm_tf32<<<dim3(6, QROWS/128),  256>>>(x,      Wq, bq, p_q);
    gemm_tf32<<<dim3(6, KVROWS/128), 256>>>(p_kvin, Wk, bk, p_k);
    gemm_tf32<<<dim3(6, KVROWS/128), 256>>>(p_kvin, Wv, bv, p_v);
    attn_kernel<<<dim3(4, NH, BATCH*NCH), 256>>>();
    gemm_tf32<<<dim3(6, QROWS/128),  256>>>(p_ctx,  Wo, bo, out);
}

// round 5
// speedup vs baseline: 4.7546x; 1.4135x over previous
#include <cuda_runtime.h>
#include <cuda_fp16.h>
#include <cstdint>

// Problem constants
#define BATCH    2
#define SEQ      8192
#define DM       768
#define NH       12
#define HD       64
#define CHUNKLEN 512
#define NLM      32
#define NCH      16           // SEQ / CHUNKLEN
#define LK       544          // NLM + CHUNKLEN
#define KVROWS   (BATCH*NCH*LK)   // 17408
#define QROWS    (BATCH*SEQ)      // 16384

// Scratch (device globals)
__device__ float g_lm[BATCH*NLM*DM];
__device__ float g_kvin[(size_t)KVROWS*DM];
__device__ float g_q[(size_t)QROWS*DM];
__device__ float g_k[(size_t)KVROWS*DM];
__device__ float g_v[(size_t)KVROWS*DM];
__device__ float g_ctx[(size_t)QROWS*DM];

// ---------------------------------------------------------------------------
// Helpers
// ---------------------------------------------------------------------------
__device__ __forceinline__ uint32_t f2h2(float lo, float hi) {
    __half2 h = __floats2half2_rn(lo, hi);   // .x = lo (low 16 bits)
    return *(uint32_t*)&h;
}

__device__ __forceinline__ void mma_f16(float c[4], const uint32_t a[4], const uint32_t b[2]) {
    asm volatile(
        "mma.sync.aligned.m16n8k16.row.col.f32.f16.f16.f32 "
        "{%0,%1,%2,%3}, {%4,%5,%6,%7}, {%8,%9}, {%0,%1,%2,%3};\n"
        : "+f"(c[0]), "+f"(c[1]), "+f"(c[2]), "+f"(c[3])
        : "r"(a[0]), "r"(a[1]), "r"(a[2]), "r"(a[3]), "r"(b[0]), "r"(b[1]));
}

__device__ __forceinline__ uint32_t cvta_shared(const void* p) {
    uint32_t a;
    asm("{ .reg .u64 t; cvta.to.shared.u64 t, %1; cvt.u32.u64 %0, t; }" : "=r"(a) : "l"(p));
    return a;
}

// ---------------------------------------------------------------------------
// 1. Landmarks: mean-pool 32 segments of 256 tokens.
// ---------------------------------------------------------------------------
__global__ void landmark_kernel(const float* __restrict__ x) {
    int b = blockIdx.x >> 5, l = blockIdx.x & 31, d = threadIdx.x;
    const float* p = x + ((size_t)(b*SEQ + l*256))*DM + d;
    float s = 0.f;
    #pragma unroll 8
    for (int t = 0; t < 256; t++) s += p[(size_t)t*DM];
    g_lm[(b*NLM + l)*DM + d] = s * (1.f/256.f);
}

// ---------------------------------------------------------------------------
// 2. Gather [landmarks ++ chunk tokens] into one dense (17408, 768) matrix.
// ---------------------------------------------------------------------------
__global__ void gather_kv_kernel(const float* __restrict__ x) {
    int idx = blockIdx.x*blockDim.x + threadIdx.x;   // float4 index
    int row = idx / 192, c = idx - row*192;
    int b   = row / (NCH*LK);
    int rem = row - b*(NCH*LK);
    int ch  = rem / LK;
    int t   = rem - ch*LK;
    float4 v;
    if (t < NLM)
        v = ((const float4*)g_lm)[(size_t)(b*NLM + t)*192 + c];
    else
        v = ((const float4*)x)[((size_t)b*SEQ + (size_t)ch*CHUNKLEN + (t-NLM))*192 + c];
    ((float4*)g_kvin)[(size_t)row*192 + c] = v;
}

// ---------------------------------------------------------------------------
// 3. fp16 tensor-core GEMM (NT): C[m,n] = bias[n] + sum_k A[m,k]*W[n,k]
//    128x128 tile, BK=32 (16 half2/row, stride 20), 256 threads, 8 warps 2x4,
//    64x32/warp via m16n8k16. blockIdx.z selects (W,bias,C) set so K and V
//    projections share one launch (and A-tiles via L2).
//    Fragment LDS bank = (20*gid + tig) mod 32 -> all distinct (conflict-free).
// ---------------------------------------------------------------------------
#define KS2 20   // half2 row stride (16 + 4 pad)

__global__ __launch_bounds__(256) void gemm_f16(
    const float* __restrict__ A,
    const float* __restrict__ W0, const float* __restrict__ b0, float* __restrict__ C0,
    const float* __restrict__ W1, const float* __restrict__ b1, float* __restrict__ C1)
{
    const float* W    = blockIdx.z ? W1 : W0;
    const float* bias = blockIdx.z ? b1 : b0;
    float*       C    = blockIdx.z ? C1 : C0;

    __shared__ __align__(16) uint32_t As[128][KS2];
    __shared__ __align__(16) uint32_t Ws[128][KS2];

    const int t    = threadIdx.x;
    const int lane = t & 31, warp = t >> 5;
    const int wm   = warp >> 2, wn = warp & 3;
    const int m0   = blockIdx.y * 128, n0 = blockIdx.x * 128;
    const int lr   = t >> 3;            // 0..31
    const int lc   = (t & 7) << 2;      // float col 0,4,...,28
    const int gid  = lane >> 2, tig = lane & 3;

    float c[4][4][4];
    #pragma unroll
    for (int mi = 0; mi < 4; mi++)
        #pragma unroll
        for (int ni = 0; ni < 4; ni++)
            #pragma unroll
            for (int r = 0; r < 4; r++) c[mi][ni][r] = 0.f;

    const float* Ag = A + (size_t)(m0 + lr) * DM + lc;
    const float* Wg = W + (size_t)(n0 + lr) * DM + lc;

    float4 pa[4], pw[4];
    #pragma unroll
    for (int i = 0; i < 4; i++) {
        pa[i] = *(const float4*)(Ag + (size_t)i*32*DM);
        pw[i] = *(const float4*)(Wg + (size_t)i*32*DM);
    }

    for (int kt = 0; kt < DM/32; kt++) {    // 24 chunks of 32 k
        #pragma unroll
        for (int i = 0; i < 4; i++) {
            uint2 ua = { f2h2(pa[i].x, pa[i].y), f2h2(pa[i].z, pa[i].w) };
            *(uint2*)&As[lr + 32*i][(t & 7) * 2] = ua;
            uint2 uw = { f2h2(pw[i].x, pw[i].y), f2h2(pw[i].z, pw[i].w) };
            *(uint2*)&Ws[lr + 32*i][(t & 7) * 2] = uw;
        }
        __syncthreads();

        if (kt < DM/32 - 1) {
            int off = (kt + 1) * 32;
            #pragma unroll
            for (int i = 0; i < 4; i++) {
                pa[i] = *(const float4*)(Ag + (size_t)i*32*DM + off);
                pw[i] = *(const float4*)(Wg + (size_t)i*32*DM + off);
            }
        }

        // 2 k-steps of k16
        #pragma unroll
        for (int kk = 0; kk < 2; kk++) {
            const int kh = kk*8 + tig;
            uint32_t a[4][4], b[4][2];
            #pragma unroll
            for (int mi = 0; mi < 4; mi++) {
                int r = wm*64 + mi*16 + gid;
                a[mi][0] = As[r    ][kh    ];
                a[mi][1] = As[r + 8][kh    ];
                a[mi][2] = As[r    ][kh + 4];
                a[mi][3] = As[r + 8][kh + 4];
            }
            #pragma unroll
            for (int ni = 0; ni < 4; ni++) {
                int n = wn*32 + ni*8 + gid;
                b[ni][0] = Ws[n][kh    ];
                b[ni][1] = Ws[n][kh + 4];
            }
            #pragma unroll
            for (int mi = 0; mi < 4; mi++)
                #pragma unroll
                for (int ni = 0; ni < 4; ni++)
                    mma_f16(c[mi][ni], a[mi], b[ni]);
        }
        __syncthreads();
    }

    #pragma unroll
    for (int mi = 0; mi < 4; mi++) {
        int r0 = m0 + wm*64 + mi*16 + gid;
        #pragma unroll
        for (int ni = 0; ni < 4; ni++) {
            int col = n0 + wn*32 + ni*8 + (tig << 1);
            float2 bv = *(const float2*)(bias + col);
            float2 o0, o1;
            o0.x = c[mi][ni][0] + bv.x; o0.y = c[mi][ni][1] + bv.y;
            o1.x = c[mi][ni][2] + bv.x; o1.y = c[mi][ni][3] + bv.y;
            *(float2*)(C + (size_t)r0*DM + col)     = o0;
            *(float2*)(C + (size_t)(r0+8)*DM + col) = o1;
        }
    }
}

// ---------------------------------------------------------------------------
// 4. fp16 tensor-core flash attention. Block = (qtile 128, head, b*chunk).
//    8 warps x 16 q-rows. KV streamed in 32-row tiles (17 tiles).
//    Ks: [kv][hd] half2, stride 36 -> conflict-free scalar B-frag loads.
//    Vs: [kv][hd] half2, stride 36 -> ldmatrix.x2.trans B-frags (row start
//        banks 4*l distinct, conflict-free).
//    Ps: [q][kv] half2 per-warp patch, stride 20 -> conflict-free A-frags.
// ---------------------------------------------------------------------------
#define AKS 36   // Ks/Vs half2 stride (32 + 4)
#define APS 20   // Ps half2 stride (16 + 4)

__global__ __launch_bounds__(256) void attn_kernel() {
    __shared__ __align__(16) uint32_t Ks[32][AKS];
    __shared__ __align__(16) uint32_t Vs[32][AKS];
    __shared__ __align__(16) uint32_t Ps[128][APS];

    const int qt = blockIdx.x, h = blockIdx.y, bc = blockIdx.z;
    const int tid  = threadIdx.x;
    const int lane = tid & 31, warp = tid >> 5;
    const int gid  = lane >> 2, tig = lane & 3;

    const int qrow0 = bc*CHUNKLEN + qt*128 + warp*16 + gid;
    const size_t kbase = (size_t)bc * LK;
    const uint32_t vs_base = cvta_shared(&Vs[0][0]);
    // ldmatrix row address component for this lane (row = lane & 15 within tile)
    const uint32_t vs_lanerow = vs_base + (uint32_t)(lane & 15) * (AKS*4);

    // Q fragments: 4 k-steps (k16) over hd=64, kept for all tiles
    uint32_t qa[4][4];
    {
        const float* qp = g_q + (size_t)qrow0*DM + h*HD;
        #pragma unroll
        for (int ks = 0; ks < 4; ks++) {
            int cc = ks*16 + 2*tig;
            qa[ks][0] = f2h2(qp[cc],                      qp[cc+1]);
            qa[ks][1] = f2h2(qp[(size_t)8*DM + cc],       qp[(size_t)8*DM + cc+1]);
            qa[ks][2] = f2h2(qp[cc+8],                    qp[cc+9]);
            qa[ks][3] = f2h2(qp[(size_t)8*DM + cc+8],     qp[(size_t)8*DM + cc+9]);
        }
    }

    float o[8][4];
    #pragma unroll
    for (int ni = 0; ni < 8; ni++)
        #pragma unroll
        for (int j = 0; j < 4; j++) o[ni][j] = 0.f;
    float m0r = -1e30f, m1r = -1e30f;
    float l0 = 0.f, l1 = 0.f;

    for (int k0 = 0; k0 < LK; k0 += 32) {
        // ---- stage K and V tiles as half2 ----
        #pragma unroll
        for (int i = 0; i < 2; i++) {
            int idx = tid + 256*i;               // 0..511 float4 of 32x64 tile
            int r = idx >> 4, c4 = (idx & 15) << 2;
            const size_t rowoff = (kbase + k0 + r)*DM + h*HD + c4;
            float4 kf = *(const float4*)(g_k + rowoff);
            uint2 ku = { f2h2(kf.x, kf.y), f2h2(kf.z, kf.w) };
            *(uint2*)&Ks[r][(idx & 15) * 2] = ku;
            float4 vf = *(const float4*)(g_v + rowoff);
            uint2 vu = { f2h2(vf.x, vf.y), f2h2(vf.z, vf.w) };
            *(uint2*)&Vs[r][(idx & 15) * 2] = vu;
        }
        __syncthreads();

        // ---- S = Q K^T * scale : 4 n-atoms x 4 k-steps ----
        float s[4][4];
        #pragma unroll
        for (int ni = 0; ni < 4; ni++)
            #pragma unroll
            for (int j = 0; j < 4; j++) s[ni][j] = 0.f;
        #pragma unroll
        for (int ks = 0; ks < 4; ks++) {
            const int kh = ks*8 + tig;
            #pragma unroll
            for (int ni = 0; ni < 4; ni++) {
                int n = ni*8 + gid;
                uint32_t b[2] = { Ks[n][kh], Ks[n][kh + 4] };
                mma_f16(s[ni], qa[ks], b);
            }
        }
        #pragma unroll
        for (int ni = 0; ni < 4; ni++)
            #pragma unroll
            for (int j = 0; j < 4; j++) s[ni][j] *= 0.125f;

        // ---- online softmax ----
        float tm0 = s[0][0], tm1 = s[0][2];
        #pragma unroll
        for (int ni = 0; ni < 4; ni++) {
            tm0 = fmaxf(tm0, fmaxf(s[ni][0], s[ni][1]));
            tm1 = fmaxf(tm1, fmaxf(s[ni][2], s[ni][3]));
        }
        tm0 = fmaxf(tm0, __shfl_xor_sync(0xffffffffu, tm0, 1));
        tm0 = fmaxf(tm0, __shfl_xor_sync(0xffffffffu, tm0, 2));
        tm1 = fmaxf(tm1, __shfl_xor_sync(0xffffffffu, tm1, 1));
        tm1 = fmaxf(tm1, __shfl_xor_sync(0xffffffffu, tm1, 2));
        float mn0 = fmaxf(m0r, tm0), mn1 = fmaxf(m1r, tm1);
        float cr0 = __expf(m0r - mn0), cr1 = __expf(m1r - mn1);
        m0r = mn0; m1r = mn1;
        l0 *= cr0; l1 *= cr1;
        #pragma unroll
        for (int ni = 0; ni < 8; ni++) {
            o[ni][0] *= cr0; o[ni][1] *= cr0;
            o[ni][2] *= cr1; o[ni][3] *= cr1;
        }

        // ---- P = exp(S - m) -> per-warp Ps patch (half2) ----
        const int pr0 = warp*16 + gid;
        #pragma unroll
        for (int ni = 0; ni < 4; ni++) {
            float p00 = __expf(s[ni][0] - mn0);
            float p01 = __expf(s[ni][1] - mn0);
            float p10 = __expf(s[ni][2] - mn1);
            float p11 = __expf(s[ni][3] - mn1);
            l0 += p00 + p01;
            l1 += p10 + p11;
            Ps[pr0    ][ni*4 + tig] = f2h2(p00, p01);
            Ps[pr0 + 8][ni*4 + tig] = f2h2(p10, p11);
        }
        __syncwarp();

        // ---- O += P V : 2 k-atoms (k16 over kv32) x 8 n-atoms ----
        #pragma unroll
        for (int ka = 0; ka < 2; ka++) {
            uint32_t a[4];
            a[0] = Ps[pr0    ][ka*8 + tig];
            a[1] = Ps[pr0 + 8][ka*8 + tig];
            a[2] = Ps[pr0    ][ka*8 + tig + 4];
            a[3] = Ps[pr0 + 8][ka*8 + tig + 4];
            const uint32_t rowaddr = vs_lanerow + (uint32_t)(16*ka) * (AKS*4);
            #pragma unroll
            for (int ni = 0; ni < 8; ni++) {
                uint32_t b[2];
                uint32_t addr = rowaddr + (uint32_t)(ni*4) * 4;   // ni*4 half2 = 16B
                asm volatile(
                    "ldmatrix.sync.aligned.m8n8.x2.trans.shared.b16 {%0,%1}, [%2];"
                    : "=r"(b[0]), "=r"(b[1]) : "r"(addr));
                mma_f16(o[ni], a, b);
            }
        }
        __syncthreads();
    }

    // ---- finalize ----
    l0 += __shfl_xor_sync(0xffffffffu, l0, 1);
    l0 += __shfl_xor_sync(0xffffffffu, l0, 2);
    l1 += __shfl_xor_sync(0xffffffffu, l1, 1);
    l1 += __shfl_xor_sync(0xffffffffu, l1, 2);
    float inv0 = 1.f / l0, inv1 = 1.f / l1;

    float* op = g_ctx + (size_t)qrow0*DM + h*HD;
    #pragma unroll
    for (int ni = 0; ni < 8; ni++) {
        int col = ni*8 + (tig << 1);
        float2 w0 = { o[ni][0]*inv0, o[ni][1]*inv0 };
        float2 w1 = { o[ni][2]*inv1, o[ni][3]*inv1 };
        *(float2*)(op + col)                = w0;
        *(float2*)(op + (size_t)8*DM + col) = w1;
    }
}

// ---------------------------------------------------------------------------
// Launch
// ---------------------------------------------------------------------------
extern "C" void kernel_launch(void* const* d_in, const int* in_sizes, int n_in,
                              void* d_out, int out_size)
{
    const float* x  = (const float*)d_in[0];
    const float* Wq = (const float*)d_in[1];
    const float* bq = (const float*)d_in[2];
    const float* Wk = (const float*)d_in[3];
    const float* bk = (const float*)d_in[4];
    const float* Wv = (const float*)d_in[5];
    const float* bv = (const float*)d_in[6];
    const float* Wo = (const float*)d_in[7];
    const float* bo = (const float*)d_in[8];
    float* out = (float*)d_out;

    float *p_kvin, *p_q, *p_k, *p_v, *p_ctx;
    cudaGetSymbolAddress((void**)&p_kvin, g_kvin);
    cudaGetSymbolAddress((void**)&p_q,    g_q);
    cudaGetSymbolAddress((void**)&p_k,    g_k);
    cudaGetSymbolAddress((void**)&p_v,    g_v);
    cudaGetSymbolAddress((void**)&p_ctx,  g_ctx);

    landmark_kernel<<<BATCH*NLM, DM>>>(x);
    gather_kv_kernel<<<(KVROWS*192)/256, 256>>>(x);
    gemm_f16<<<dim3(6, QROWS/128, 1),  256>>>(x, Wq, bq, p_q, Wq, bq, p_q);
    gemm_f16<<<dim3(6, KVROWS/128, 2), 256>>>(p_kvin, Wk, bk, p_k, Wv, bv, p_v);
    attn_kernel<<<dim3(4, NH, BATCH*NCH), 256>>>();
    gemm_f16<<<dim3(6, QROWS/128, 1),  256>>>(p_ctx, Wo, bo, out, Wo, bo, out);
}

// round 6
// speedup vs baseline: 4.7802x; 1.0054x over previous
#include <cuda_runtime.h>
#include <cuda_fp16.h>
#include <cstdint>

// Problem constants
#define BATCH    2
#define SEQ      8192
#define DM       768
#define NH       12
#define HD       64
#define CHUNKLEN 512
#define NLM      32
#define NCH      16           // SEQ / CHUNKLEN
#define LK       544          // NLM + CHUNKLEN
#define KVROWS   (BATCH*NCH*LK)   // 17408
#define QROWS    (BATCH*SEQ)      // 16384

// Scratch (device globals)
__device__ float g_lm[BATCH*NLM*DM];
__device__ float g_kvin[(size_t)KVROWS*DM];
__device__ float g_q[(size_t)QROWS*DM];
__device__ float g_k[(size_t)KVROWS*DM];
__device__ float g_v[(size_t)KVROWS*DM];
__device__ float g_ctx[(size_t)QROWS*DM];

// ---------------------------------------------------------------------------
// Helpers
// ---------------------------------------------------------------------------
__device__ __forceinline__ uint32_t f2h2(float lo, float hi) {
    __half2 h = __floats2half2_rn(lo, hi);   // .x = lo (low 16 bits)
    return *(uint32_t*)&h;
}

__device__ __forceinline__ void mma_f16(float c[4], const uint32_t a[4], const uint32_t b[2]) {
    asm volatile(
        "mma.sync.aligned.m16n8k16.row.col.f32.f16.f16.f32 "
        "{%0,%1,%2,%3}, {%4,%5,%6,%7}, {%8,%9}, {%0,%1,%2,%3};\n"
        : "+f"(c[0]), "+f"(c[1]), "+f"(c[2]), "+f"(c[3])
        : "r"(a[0]), "r"(a[1]), "r"(a[2]), "r"(a[3]), "r"(b[0]), "r"(b[1]));
}

__device__ __forceinline__ uint32_t cvta_shared(const void* p) {
    uint32_t a;
    asm("{ .reg .u64 t; cvta.to.shared.u64 t, %1; cvt.u32.u64 %0, t; }" : "=r"(a) : "l"(p));
    return a;
}

// ---------------------------------------------------------------------------
// 1. Landmarks: mean-pool 32 segments of 256 tokens.
// ---------------------------------------------------------------------------
__global__ void landmark_kernel(const float* __restrict__ x) {
    int b = blockIdx.x >> 5, l = blockIdx.x & 31, d = threadIdx.x;
    const float* p = x + ((size_t)(b*SEQ + l*256))*DM + d;
    float s = 0.f;
    #pragma unroll 8
    for (int t = 0; t < 256; t++) s += p[(size_t)t*DM];
    g_lm[(b*NLM + l)*DM + d] = s * (1.f/256.f);
}

// ---------------------------------------------------------------------------
// 2. Gather [landmarks ++ chunk tokens] into one dense (17408, 768) matrix.
// ---------------------------------------------------------------------------
__global__ void gather_kv_kernel(const float* __restrict__ x) {
    int idx = blockIdx.x*blockDim.x + threadIdx.x;   // float4 index
    int row = idx / 192, c = idx - row*192;
    int b   = row / (NCH*LK);
    int rem = row - b*(NCH*LK);
    int ch  = rem / LK;
    int t   = rem - ch*LK;
    float4 v;
    if (t < NLM)
        v = ((const float4*)g_lm)[(size_t)(b*NLM + t)*192 + c];
    else
        v = ((const float4*)x)[((size_t)b*SEQ + (size_t)ch*CHUNKLEN + (t-NLM))*192 + c];
    ((float4*)g_kvin)[(size_t)row*192 + c] = v;
}

// ---------------------------------------------------------------------------
// 3. fp16 tensor-core GEMM (NT): C[m,n] = bias[n] + sum_k A[m,k]*W[n,k]
//    128x128 tile, BK=32 (16 half2/row, stride 20), 256 threads, 8 warps 2x4,
//    64x32/warp via m16n8k16. blockIdx.z selects (W,bias,C) set so K and V
//    projections share one launch (and A-tiles via L2).
//    Fragment LDS bank = (20*gid + tig) mod 32 -> all distinct (conflict-free).
// ---------------------------------------------------------------------------
#define KS2 20   // half2 row stride (16 + 4 pad)

__global__ __launch_bounds__(256) void gemm_f16(
    const float* __restrict__ A,
    const float* __restrict__ W0, const float* __restrict__ b0, float* __restrict__ C0,
    const float* __restrict__ W1, const float* __restrict__ b1, float* __restrict__ C1)
{
    const float* W    = blockIdx.z ? W1 : W0;
    const float* bias = blockIdx.z ? b1 : b0;
    float*       C    = blockIdx.z ? C1 : C0;

    __shared__ __align__(16) uint32_t As[128][KS2];
    __shared__ __align__(16) uint32_t Ws[128][KS2];

    const int t    = threadIdx.x;
    const int lane = t & 31, warp = t >> 5;
    const int wm   = warp >> 2, wn = warp & 3;
    const int m0   = blockIdx.y * 128, n0 = blockIdx.x * 128;
    const int lr   = t >> 3;            // 0..31
    const int lc   = (t & 7) << 2;      // float col 0,4,...,28
    const int gid  = lane >> 2, tig = lane & 3;

    float c[4][4][4];
    #pragma unroll
    for (int mi = 0; mi < 4; mi++)
        #pragma unroll
        for (int ni = 0; ni < 4; ni++)
            #pragma unroll
            for (int r = 0; r < 4; r++) c[mi][ni][r] = 0.f;

    const float* Ag = A + (size_t)(m0 + lr) * DM + lc;
    const float* Wg = W + (size_t)(n0 + lr) * DM + lc;

    float4 pa[4], pw[4];
    #pragma unroll
    for (int i = 0; i < 4; i++) {
        pa[i] = *(const float4*)(Ag + (size_t)i*32*DM);
        pw[i] = *(const float4*)(Wg + (size_t)i*32*DM);
    }

    for (int kt = 0; kt < DM/32; kt++) {    // 24 chunks of 32 k
        #pragma unroll
        for (int i = 0; i < 4; i++) {
            uint2 ua = { f2h2(pa[i].x, pa[i].y), f2h2(pa[i].z, pa[i].w) };
            *(uint2*)&As[lr + 32*i][(t & 7) * 2] = ua;
            uint2 uw = { f2h2(pw[i].x, pw[i].y), f2h2(pw[i].z, pw[i].w) };
            *(uint2*)&Ws[lr + 32*i][(t & 7) * 2] = uw;
        }
        __syncthreads();

        if (kt < DM/32 - 1) {
            int off = (kt + 1) * 32;
            #pragma unroll
            for (int i = 0; i < 4; i++) {
                pa[i] = *(const float4*)(Ag + (size_t)i*32*DM + off);
                pw[i] = *(const float4*)(Wg + (size_t)i*32*DM + off);
            }
        }

        // 2 k-steps of k16
        #pragma unroll
        for (int kk = 0; kk < 2; kk++) {
            const int kh = kk*8 + tig;
            uint32_t a[4][4], b[4][2];
            #pragma unroll
            for (int mi = 0; mi < 4; mi++) {
                int r = wm*64 + mi*16 + gid;
                a[mi][0] = As[r    ][kh    ];
                a[mi][1] = As[r + 8][kh    ];
                a[mi][2] = As[r    ][kh + 4];
                a[mi][3] = As[r + 8][kh + 4];
            }
            #pragma unroll
            for (int ni = 0; ni < 4; ni++) {
                int n = wn*32 + ni*8 + gid;
                b[ni][0] = Ws[n][kh    ];
                b[ni][1] = Ws[n][kh + 4];
            }
            #pragma unroll
            for (int mi = 0; mi < 4; mi++)
                #pragma unroll
                for (int ni = 0; ni < 4; ni++)
                    mma_f16(c[mi][ni], a[mi], b[ni]);
        }
        __syncthreads();
    }

    #pragma unroll
    for (int mi = 0; mi < 4; mi++) {
        int r0 = m0 + wm*64 + mi*16 + gid;
        #pragma unroll
        for (int ni = 0; ni < 4; ni++) {
            int col = n0 + wn*32 + ni*8 + (tig << 1);
            float2 bv = *(const float2*)(bias + col);
            float2 o0, o1;
            o0.x = c[mi][ni][0] + bv.x; o0.y = c[mi][ni][1] + bv.y;
            o1.x = c[mi][ni][2] + bv.x; o1.y = c[mi][ni][3] + bv.y;
            *(float2*)(C + (size_t)r0*DM + col)     = o0;
            *(float2*)(C + (size_t)(r0+8)*DM + col) = o1;
        }
    }
}

// ---------------------------------------------------------------------------
// 4. fp16 tensor-core flash attention. Block = (qtile 128, head, b*chunk).
//    8 warps x 16 q-rows. KV streamed in 32-row tiles (17 tiles).
//    Ks: [kv][hd] half2, stride 36 -> conflict-free scalar B-frag loads.
//    Vs: [kv][hd] half2, stride 36 -> ldmatrix.x2.trans B-frags (row start
//        banks 4*l distinct, conflict-free).
//    Ps: [q][kv] half2 per-warp patch, stride 20 -> conflict-free A-frags.
// ---------------------------------------------------------------------------
#define AKS 36   // Ks/Vs half2 stride (32 + 4)
#define APS 20   // Ps half2 stride (16 + 4)

__global__ __launch_bounds__(256) void attn_kernel() {
    __shared__ __align__(16) uint32_t Ks[32][AKS];
    __shared__ __align__(16) uint32_t Vs[32][AKS];
    __shared__ __align__(16) uint32_t Ps[128][APS];

    const int qt = blockIdx.x, h = blockIdx.y, bc = blockIdx.z;
    const int tid  = threadIdx.x;
    const int lane = tid & 31, warp = tid >> 5;
    const int gid  = lane >> 2, tig = lane & 3;

    const int qrow0 = bc*CHUNKLEN + qt*128 + warp*16 + gid;
    const size_t kbase = (size_t)bc * LK;
    const uint32_t vs_base = cvta_shared(&Vs[0][0]);
    // ldmatrix row address component for this lane (row = lane & 15 within tile)
    const uint32_t vs_lanerow = vs_base + (uint32_t)(lane & 15) * (AKS*4);

    // Q fragments: 4 k-steps (k16) over hd=64, kept for all tiles
    uint32_t qa[4][4];
    {
        const float* qp = g_q + (size_t)qrow0*DM + h*HD;
        #pragma unroll
        for (int ks = 0; ks < 4; ks++) {
            int cc = ks*16 + 2*tig;
            qa[ks][0] = f2h2(qp[cc],                      qp[cc+1]);
            qa[ks][1] = f2h2(qp[(size_t)8*DM + cc],       qp[(size_t)8*DM + cc+1]);
            qa[ks][2] = f2h2(qp[cc+8],                    qp[cc+9]);
            qa[ks][3] = f2h2(qp[(size_t)8*DM + cc+8],     qp[(size_t)8*DM + cc+9]);
        }
    }

    float o[8][4];
    #pragma unroll
    for (int ni = 0; ni < 8; ni++)
        #pragma unroll
        for (int j = 0; j < 4; j++) o[ni][j] = 0.f;
    float m0r = -1e30f, m1r = -1e30f;
    float l0 = 0.f, l1 = 0.f;

    for (int k0 = 0; k0 < LK; k0 += 32) {
        // ---- stage K and V tiles as half2 ----
        #pragma unroll
        for (int i = 0; i < 2; i++) {
            int idx = tid + 256*i;               // 0..511 float4 of 32x64 tile
            int r = idx >> 4, c4 = (idx & 15) << 2;
            const size_t rowoff = (kbase + k0 + r)*DM + h*HD + c4;
            float4 kf = *(const float4*)(g_k + rowoff);
            uint2 ku = { f2h2(kf.x, kf.y), f2h2(kf.z, kf.w) };
            *(uint2*)&Ks[r][(idx & 15) * 2] = ku;
            float4 vf = *(const float4*)(g_v + rowoff);
            uint2 vu = { f2h2(vf.x, vf.y), f2h2(vf.z, vf.w) };
            *(uint2*)&Vs[r][(idx & 15) * 2] = vu;
        }
        __syncthreads();

        // ---- S = Q K^T * scale : 4 n-atoms x 4 k-steps ----
        float s[4][4];
        #pragma unroll
        for (int ni = 0; ni < 4; ni++)
            #pragma unroll
            for (int j = 0; j < 4; j++) s[ni][j] = 0.f;
        #pragma unroll
        for (int ks = 0; ks < 4; ks++) {
            const int kh = ks*8 + tig;
            #pragma unroll
            for (int ni = 0; ni < 4; ni++) {
                int n = ni*8 + gid;
                uint32_t b[2] = { Ks[n][kh], Ks[n][kh + 4] };
                mma_f16(s[ni], qa[ks], b);
            }
        }
        #pragma unroll
        for (int ni = 0; ni < 4; ni++)
            #pragma unroll
            for (int j = 0; j < 4; j++) s[ni][j] *= 0.125f;

        // ---- online softmax ----
        float tm0 = s[0][0], tm1 = s[0][2];
        #pragma unroll
        for (int ni = 0; ni < 4; ni++) {
            tm0 = fmaxf(tm0, fmaxf(s[ni][0], s[ni][1]));
            tm1 = fmaxf(tm1, fmaxf(s[ni][2], s[ni][3]));
        }
        tm0 = fmaxf(tm0, __shfl_xor_sync(0xffffffffu, tm0, 1));
        tm0 = fmaxf(tm0, __shfl_xor_sync(0xffffffffu, tm0, 2));
        tm1 = fmaxf(tm1, __shfl_xor_sync(0xffffffffu, tm1, 1));
        tm1 = fmaxf(tm1, __shfl_xor_sync(0xffffffffu, tm1, 2));
        float mn0 = fmaxf(m0r, tm0), mn1 = fmaxf(m1r, tm1);
        float cr0 = __expf(m0r - mn0), cr1 = __expf(m1r - mn1);
        m0r = mn0; m1r = mn1;
        l0 *= cr0; l1 *= cr1;
        #pragma unroll
        for (int ni = 0; ni < 8; ni++) {
            o[ni][0] *= cr0; o[ni][1] *= cr0;
            o[ni][2] *= cr1; o[ni][3] *= cr1;
        }

        // ---- P = exp(S - m) -> per-warp Ps patch (half2) ----
        const int pr0 = warp*16 + gid;
        #pragma unroll
        for (int ni = 0; ni < 4; ni++) {
            float p00 = __expf(s[ni][0] - mn0);
            float p01 = __expf(s[ni][1] - mn0);
            float p10 = __expf(s[ni][2] - mn1);
            float p11 = __expf(s[ni][3] - mn1);
            l0 += p00 + p01;
            l1 += p10 + p11;
            Ps[pr0    ][ni*4 + tig] = f2h2(p00, p01);
            Ps[pr0 + 8][ni*4 + tig] = f2h2(p10, p11);
        }
        __syncwarp();

        // ---- O += P V : 2 k-atoms (k16 over kv32) x 8 n-atoms ----
        #pragma unroll
        for (int ka = 0; ka < 2; ka++) {
            uint32_t a[4];
            a[0] = Ps[pr0    ][ka*8 + tig];
            a[1] = Ps[pr0 + 8][ka*8 + tig];
            a[2] = Ps[pr0    ][ka*8 + tig + 4];
            a[3] = Ps[pr0 + 8][ka*8 + tig + 4];
            const uint32_t rowaddr = vs_lanerow + (uint32_t)(16*ka) * (AKS*4);
            #pragma unroll
            for (int ni = 0; ni < 8; ni++) {
                uint32_t b[2];
                uint32_t addr = rowaddr + (uint32_t)(ni*4) * 4;   // ni*4 half2 = 16B
                asm volatile(
                    "ldmatrix.sync.aligned.m8n8.x2.trans.shared.b16 {%0,%1}, [%2];"
                    : "=r"(b[0]), "=r"(b[1]) : "r"(addr));
                mma_f16(o[ni], a, b);
            }
        }
        __syncthreads();
    }

    // ---- finalize ----
    l0 += __shfl_xor_sync(0xffffffffu, l0, 1);
    l0 += __shfl_xor_sync(0xffffffffu, l0, 2);
    l1 += __shfl_xor_sync(0xffffffffu, l1, 1);
    l1 += __shfl_xor_sync(0xffffffffu, l1, 2);
    float inv0 = 1.f / l0, inv1 = 1.f / l1;

    float* op = g_ctx + (size_t)qrow0*DM + h*HD;
    #pragma unroll
    for (int ni = 0; ni < 8; ni++) {
        int col = ni*8 + (tig << 1);
        float2 w0 = { o[ni][0]*inv0, o[ni][1]*inv0 };
        float2 w1 = { o[ni][2]*inv1, o[ni][3]*inv1 };
        *(float2*)(op + col)                = w0;
        *(float2*)(op + (size_t)8*DM + col) = w1;
    }
}

// ---------------------------------------------------------------------------
// Launch
// ---------------------------------------------------------------------------
extern "C" void kernel_launch(void* const* d_in, const int* in_sizes, int n_in,
                              void* d_out, int out_size)
{
    const float* x  = (const float*)d_in[0];
    const float* Wq = (const float*)d_in[1];
    const float* bq = (const float*)d_in[2];
    const float* Wk = (const float*)d_in[3];
    const float* bk = (const float*)d_in[4];
    const float* Wv = (const float*)d_in[5];
    const float* bv = (const float*)d_in[6];
    const float* Wo = (const float*)d_in[7];
    const float* bo = (const float*)d_in[8];
    float* out = (float*)d_out;

    float *p_kvin, *p_q, *p_k, *p_v, *p_ctx;
    cudaGetSymbolAddress((void**)&p_kvin, g_kvin);
    cudaGetSymbolAddress((void**)&p_q,    g_q);
    cudaGetSymbolAddress((void**)&p_k,    g_k);
    cudaGetSymbolAddress((void**)&p_v,    g_v);
    cudaGetSymbolAddress((void**)&p_ctx,  g_ctx);

    landmark_kernel<<<BATCH*NLM, DM>>>(x);
    gather_kv_kernel<<<(KVROWS*192)/256, 256>>>(x);
    gemm_f16<<<dim3(6, QROWS/128, 1),  256>>>(x, Wq, bq, p_q, Wq, bq, p_q);
    gemm_f16<<<dim3(6, KVROWS/128, 2), 256>>>(p_kvin, Wk, bk, p_k, Wv, bv, p_v);
    attn_kernel<<<dim3(4, NH, BATCH*NCH), 256>>>();
    gemm_f16<<<dim3(6, QROWS/128, 1),  256>>>(p_ctx, Wo, bo, out, Wo, bo, out);
}

// round 7
// speedup vs baseline: 5.9737x; 1.2497x over previous
#include <cuda_runtime.h>
#include <cuda_fp16.h>
#include <cstdint>

// Problem constants
#define BATCH    2
#define SEQ      8192
#define DM       768
#define NH       12
#define HD       64
#define CHUNKLEN 512
#define NLM      32
#define NCH      16           // SEQ / CHUNKLEN
#define LK       544          // NLM + CHUNKLEN
#define KVROWS   (BATCH*NCH*LK)   // 17408
#define QROWS    (BATCH*SEQ)      // 16384

// Scratch (device globals)
__device__ float g_lm[BATCH*NLM*DM];
__device__ __align__(16) __half g_xh  [(size_t)QROWS*DM];
__device__ __align__(16) __half g_kvh [(size_t)KVROWS*DM];
__device__ __align__(16) __half g_qh  [(size_t)QROWS*DM];
__device__ __align__(16) __half g_kh  [(size_t)KVROWS*DM];
__device__ __align__(16) __half g_vh  [(size_t)KVROWS*DM];
__device__ __align__(16) __half g_ctxh[(size_t)QROWS*DM];
__device__ __align__(16) __half g_wq[DM*DM], g_wk[DM*DM], g_wv[DM*DM], g_wo[DM*DM];

// ---------------------------------------------------------------------------
// Helpers
// ---------------------------------------------------------------------------
__device__ __forceinline__ uint32_t f2h2(float lo, float hi) {
    __half2 h = __floats2half2_rn(lo, hi);
    return *(uint32_t*)&h;
}

__device__ __forceinline__ void mma_f16(float c[4], const uint32_t a[4], const uint32_t b[2]) {
    asm volatile(
        "mma.sync.aligned.m16n8k16.row.col.f32.f16.f16.f32 "
        "{%0,%1,%2,%3}, {%4,%5,%6,%7}, {%8,%9}, {%0,%1,%2,%3};\n"
        : "+f"(c[0]), "+f"(c[1]), "+f"(c[2]), "+f"(c[3])
        : "r"(a[0]), "r"(a[1]), "r"(a[2]), "r"(a[3]), "r"(b[0]), "r"(b[1]));
}

__device__ __forceinline__ uint32_t cvta_shared(const void* p) {
    uint32_t a;
    asm("{ .reg .u64 t; cvta.to.shared.u64 t, %1; cvt.u32.u64 %0, t; }" : "=r"(a) : "l"(p));
    return a;
}

__device__ __forceinline__ void cp16(uint32_t dst, const void* src) {
    asm volatile("cp.async.cg.shared.global [%0], [%1], 16;" :: "r"(dst), "l"(src) : "memory");
}
#define CP_COMMIT() asm volatile("cp.async.commit_group;" ::: "memory")
#define CP_WAIT0()  asm volatile("cp.async.wait_group 0;" ::: "memory")

// ---------------------------------------------------------------------------
// 0. fp32 -> fp16 conversion (x and weights), 4 elems/thread
// ---------------------------------------------------------------------------
__global__ void cvt_f2h(const float* __restrict__ s, __half* __restrict__ d) {
    int i = blockIdx.x*blockDim.x + threadIdx.x;
    float4 v = ((const float4*)s)[i];
    uint2 u = { f2h2(v.x, v.y), f2h2(v.z, v.w) };
    ((uint2*)d)[i] = u;
}

// ---------------------------------------------------------------------------
// 1. Landmarks: mean-pool 32 segments of 256 tokens (fp32).
// ---------------------------------------------------------------------------
__global__ void landmark_kernel(const float* __restrict__ x) {
    int b = blockIdx.x >> 5, l = blockIdx.x & 31, d = threadIdx.x;
    const float* p = x + ((size_t)(b*SEQ + l*256))*DM + d;
    float s = 0.f;
    #pragma unroll 8
    for (int t = 0; t < 256; t++) s += p[(size_t)t*DM];
    g_lm[(b*NLM + l)*DM + d] = s * (1.f/256.f);
}

// ---------------------------------------------------------------------------
// 2. Gather [landmarks ++ chunk] into dense (17408, 768) half matrix.
// ---------------------------------------------------------------------------
__global__ void gather_kv_h(const float* __restrict__ x) {
    int idx = blockIdx.x*blockDim.x + threadIdx.x;   // float4 granule
    int row = idx / 192, c = idx - row*192;
    int b   = row / (NCH*LK);
    int rem = row - b*(NCH*LK);
    int ch  = rem / LK;
    int t   = rem - ch*LK;
    float4 v;
    if (t < NLM)
        v = ((const float4*)g_lm)[(size_t)(b*NLM + t)*192 + c];
    else
        v = ((const float4*)x)[((size_t)b*SEQ + (size_t)ch*CHUNKLEN + (t-NLM))*192 + c];
    uint2 u = { f2h2(v.x, v.y), f2h2(v.z, v.w) };
    ((uint2*)g_kvh)[(size_t)row*192 + c] = u;
}

// ---------------------------------------------------------------------------
// 3. fp16 GEMM (NT) with cp.async 2-stage pipeline.
//    C[m,n] = bias[n] + sum_k A[m,k]*W[n,k], K=768 in 12 chunks of 64.
//    128x128 tile, 256 threads, 8 warps (2x4), 64x32/warp m16n8k16.
//    Smem rows padded to 144B (36 u32, =4 mod 32 -> conflict-free frags,
//    16B-aligned for cp.async). One __syncthreads per chunk; load(kt+1)
//    overlaps compute(kt). Dynamic smem 72KB, 2 CTAs/SM.
// ---------------------------------------------------------------------------
struct GArgs {
    const __half* A; const __half* W; const float* bias;
    __half* Ch; float* Cf; int M;
};

#define GT_U32   4608            // 128 rows * 36 u32 per tile
#define GBUF_U32 9216            // A tile + W tile per stage
#define GEMM_SMEM (2*GBUF_U32*4) // 73728 bytes

__global__ __launch_bounds__(256, 2) void gemm_h(GArgs a0, GArgs a1, GArgs a2) {
    const GArgs ga = (blockIdx.z == 0) ? a0 : (blockIdx.z == 1 ? a1 : a2);
    const int m0 = blockIdx.y * 128;
    if (m0 >= ga.M) return;
    const int n0 = blockIdx.x * 128;

    extern __shared__ __align__(16) uint32_t dsm[];
    const uint32_t sb = cvta_shared(dsm);

    const int tid  = threadIdx.x;
    const int lane = tid & 31, warp = tid >> 5;
    const int wm   = warp >> 2, wn = warp & 3;
    const int gid  = lane >> 2, tig = lane & 3;
    const int sr   = tid >> 3, sg = tid & 7;        // staging row/granule

    float c[4][4][4];
    #pragma unroll
    for (int mi = 0; mi < 4; mi++)
        #pragma unroll
        for (int ni = 0; ni < 4; ni++)
            #pragma unroll
            for (int r = 0; r < 4; r++) c[mi][ni][r] = 0.f;

    const __half* Asrc = ga.A + (size_t)(m0 + sr)*DM + sg*8;
    const __half* Wsrc = ga.W + (size_t)(n0 + sr)*DM + sg*8;
    const uint32_t dbase = sb + (uint32_t)(sr*144 + sg*16);

    auto stage = [&](int kt, int b) {
        const uint32_t da = dbase + (uint32_t)b * (GBUF_U32*4);
        const uint32_t dw = da + GT_U32*4;
        const __half* as = Asrc + kt*64;
        const __half* ws = Wsrc + kt*64;
        #pragma unroll
        for (int i = 0; i < 4; i++) {
            cp16(da + i*32*144, as + (size_t)i*32*DM);
            cp16(dw + i*32*144, ws + (size_t)i*32*DM);
        }
    };

    stage(0, 0);
    CP_COMMIT();

    for (int kt = 0; kt < DM/64; kt++) {       // 12 chunks
        CP_WAIT0();
        __syncthreads();
        if (kt + 1 < DM/64) { stage(kt + 1, (kt + 1) & 1); CP_COMMIT(); }

        const uint32_t* Ab = dsm + (kt & 1) * GBUF_U32;
        const uint32_t* Wb = Ab + GT_U32;
        #pragma unroll
        for (int ks = 0; ks < 4; ks++) {
            const int kh = ks*8 + tig;
            uint32_t a[4][4], b[4][2];
            #pragma unroll
            for (int mi = 0; mi < 4; mi++) {
                const uint32_t* Ar = Ab + (wm*64 + mi*16 + gid)*36;
                a[mi][0] = Ar[kh];
                a[mi][1] = Ar[8*36 + kh];
                a[mi][2] = Ar[kh + 4];
                a[mi][3] = Ar[8*36 + kh + 4];
            }
            #pragma unroll
            for (int ni = 0; ni < 4; ni++) {
                const uint32_t* Wr = Wb + (wn*32 + ni*8 + gid)*36;
                b[ni][0] = Wr[kh];
                b[ni][1] = Wr[kh + 4];
            }
            #pragma unroll
            for (int mi = 0; mi < 4; mi++)
                #pragma unroll
                for (int ni = 0; ni < 4; ni++)
                    mma_f16(c[mi][ni], a[mi], b[ni]);
        }
    }

    // epilogue: bias (fp32) + store half or float
    #pragma unroll
    for (int mi = 0; mi < 4; mi++) {
        int r0 = m0 + wm*64 + mi*16 + gid;
        #pragma unroll
        for (int ni = 0; ni < 4; ni++) {
            int col = n0 + wn*32 + ni*8 + (tig << 1);
            float2 bv = *(const float2*)(ga.bias + col);
            float v00 = c[mi][ni][0] + bv.x, v01 = c[mi][ni][1] + bv.y;
            float v10 = c[mi][ni][2] + bv.x, v11 = c[mi][ni][3] + bv.y;
            if (ga.Cf) {
                *(float2*)(ga.Cf + (size_t)r0*DM + col)     = make_float2(v00, v01);
                *(float2*)(ga.Cf + (size_t)(r0+8)*DM + col) = make_float2(v10, v11);
            } else {
                *(uint32_t*)(ga.Ch + (size_t)r0*DM + col)     = f2h2(v00, v01);
                *(uint32_t*)(ga.Ch + (size_t)(r0+8)*DM + col) = f2h2(v10, v11);
            }
        }
    }
}

// ---------------------------------------------------------------------------
// 4. fp16 flash attention, cp.async double-buffered KV staging.
//    Block = (qtile 128, head, b*chunk); 8 warps x 16 q-rows; 17 KV tiles.
//    Ks/Vs [2][32][36] u32 (144B rows): conflict-free scalar K-frags and
//    ldmatrix.trans V-frags. Ps [128][20] per-warp patch.
// ---------------------------------------------------------------------------
__global__ __launch_bounds__(256) void attn_kernel() {
    __shared__ __align__(16) uint32_t Ks[2][32][36];
    __shared__ __align__(16) uint32_t Vs[2][32][36];
    __shared__ __align__(16) uint32_t Ps[128][20];

    const int qt = blockIdx.x, h = blockIdx.y, bc = blockIdx.z;
    const int tid  = threadIdx.x;
    const int lane = tid & 31, warp = tid >> 5;
    const int gid  = lane >> 2, tig = lane & 3;

    const int qrow0 = bc*CHUNKLEN + qt*128 + warp*16 + gid;
    const size_t kbase = (size_t)bc * LK;
    const int sr = tid >> 3, sg = tid & 7;

    const uint32_t ks_sb = cvta_shared(&Ks[0][0][0]);
    const uint32_t vs_sb = cvta_shared(&Vs[0][0][0]);
    const uint32_t kv_doff = (uint32_t)(sr*144 + sg*16);

    auto stage = [&](int t, int b) {
        const size_t rowoff = (kbase + (size_t)t*32 + sr)*DM + h*HD + sg*8;
        cp16(ks_sb + b*(32*144) + kv_doff, g_kh + rowoff);
        cp16(vs_sb + b*(32*144) + kv_doff, g_vh + rowoff);
    };

    // Q fragments (half, direct 32-bit loads), kept for all tiles
    uint32_t qa[4][4];
    {
        const __half* qp = g_qh + (size_t)qrow0*DM + h*HD;
        #pragma unroll
        for (int ks = 0; ks < 4; ks++) {
            int cc = ks*16 + 2*tig;
            qa[ks][0] = *(const uint32_t*)(qp + cc);
            qa[ks][1] = *(const uint32_t*)(qp + (size_t)8*DM + cc);
            qa[ks][2] = *(const uint32_t*)(qp + cc + 8);
            qa[ks][3] = *(const uint32_t*)(qp + (size_t)8*DM + cc + 8);
        }
    }

    float o[8][4];
    #pragma unroll
    for (int ni = 0; ni < 8; ni++)
        #pragma unroll
        for (int j = 0; j < 4; j++) o[ni][j] = 0.f;
    float m0r = -1e30f, m1r = -1e30f;
    float l0 = 0.f, l1 = 0.f;

    stage(0, 0);
    CP_COMMIT();

    for (int t = 0; t < LK/32; t++) {          // 17 tiles
        CP_WAIT0();
        __syncthreads();
        if (t + 1 < LK/32) { stage(t + 1, (t + 1) & 1); CP_COMMIT(); }
        const int b = t & 1;

        // ---- S = Q K^T * scale ----
        float s[4][4];
        #pragma unroll
        for (int ni = 0; ni < 4; ni++)
            #pragma unroll
            for (int j = 0; j < 4; j++) s[ni][j] = 0.f;
        #pragma unroll
        for (int ks = 0; ks < 4; ks++) {
            const int kh = ks*8 + tig;
            #pragma unroll
            for (int ni = 0; ni < 4; ni++) {
                int n = ni*8 + gid;
                uint32_t bf[2] = { Ks[b][n][kh], Ks[b][n][kh + 4] };
                mma_f16(s[ni], qa[ks], bf);
            }
        }
        #pragma unroll
        for (int ni = 0; ni < 4; ni++)
            #pragma unroll
            for (int j = 0; j < 4; j++) s[ni][j] *= 0.125f;

        // ---- online softmax ----
        float tm0 = s[0][0], tm1 = s[0][2];
        #pragma unroll
        for (int ni = 0; ni < 4; ni++) {
            tm0 = fmaxf(tm0, fmaxf(s[ni][0], s[ni][1]));
            tm1 = fmaxf(tm1, fmaxf(s[ni][2], s[ni][3]));
        }
        tm0 = fmaxf(tm0, __shfl_xor_sync(0xffffffffu, tm0, 1));
        tm0 = fmaxf(tm0, __shfl_xor_sync(0xffffffffu, tm0, 2));
        tm1 = fmaxf(tm1, __shfl_xor_sync(0xffffffffu, tm1, 1));
        tm1 = fmaxf(tm1, __shfl_xor_sync(0xffffffffu, tm1, 2));
        float mn0 = fmaxf(m0r, tm0), mn1 = fmaxf(m1r, tm1);
        float cr0 = __expf(m0r - mn0), cr1 = __expf(m1r - mn1);
        m0r = mn0; m1r = mn1;
        l0 *= cr0; l1 *= cr1;
        #pragma unroll
        for (int ni = 0; ni < 8; ni++) {
            o[ni][0] *= cr0; o[ni][1] *= cr0;
            o[ni][2] *= cr1; o[ni][3] *= cr1;
        }

        // ---- P = exp(S - m) -> per-warp Ps patch ----
        const int pr0 = warp*16 + gid;
        #pragma unroll
        for (int ni = 0; ni < 4; ni++) {
            float p00 = __expf(s[ni][0] - mn0);
            float p01 = __expf(s[ni][1] - mn0);
            float p10 = __expf(s[ni][2] - mn1);
            float p11 = __expf(s[ni][3] - mn1);
            l0 += p00 + p01;
            l1 += p10 + p11;
            Ps[pr0    ][ni*4 + tig] = f2h2(p00, p01);
            Ps[pr0 + 8][ni*4 + tig] = f2h2(p10, p11);
        }
        __syncwarp();

        // ---- O += P V (ldmatrix.trans B-frags) ----
        const uint32_t vs_lanerow = vs_sb + b*(32*144) + (uint32_t)(lane & 15)*144;
        #pragma unroll
        for (int ka = 0; ka < 2; ka++) {
            uint32_t a[4];
            a[0] = Ps[pr0    ][ka*8 + tig];
            a[1] = Ps[pr0 + 8][ka*8 + tig];
            a[2] = Ps[pr0    ][ka*8 + tig + 4];
            a[3] = Ps[pr0 + 8][ka*8 + tig + 4];
            const uint32_t rowaddr = vs_lanerow + (uint32_t)(16*ka)*144;
            #pragma unroll
            for (int ni = 0; ni < 8; ni++) {
                uint32_t bf[2];
                uint32_t addr = rowaddr + (uint32_t)(ni*16);
                asm volatile(
                    "ldmatrix.sync.aligned.m8n8.x2.trans.shared.b16 {%0,%1}, [%2];"
                    : "=r"(bf[0]), "=r"(bf[1]) : "r"(addr));
                mma_f16(o[ni], a, bf);
            }
        }
    }

    // ---- finalize: write ctx as half ----
    l0 += __shfl_xor_sync(0xffffffffu, l0, 1);
    l0 += __shfl_xor_sync(0xffffffffu, l0, 2);
    l1 += __shfl_xor_sync(0xffffffffu, l1, 1);
    l1 += __shfl_xor_sync(0xffffffffu, l1, 2);
    float inv0 = 1.f / l0, inv1 = 1.f / l1;

    __half* op = g_ctxh + (size_t)qrow0*DM + h*HD;
    #pragma unroll
    for (int ni = 0; ni < 8; ni++) {
        int col = ni*8 + (tig << 1);
        *(uint32_t*)(op + col)                = f2h2(o[ni][0]*inv0, o[ni][1]*inv0);
        *(uint32_t*)(op + (size_t)8*DM + col) = f2h2(o[ni][2]*inv1, o[ni][3]*inv1);
    }
}

// ---------------------------------------------------------------------------
// Launch
// ---------------------------------------------------------------------------
extern "C" void kernel_launch(void* const* d_in, const int* in_sizes, int n_in,
                              void* d_out, int out_size)
{
    const float* x  = (const float*)d_in[0];
    const float* Wq = (const float*)d_in[1];
    const float* bq = (const float*)d_in[2];
    const float* Wk = (const float*)d_in[3];
    const float* bk = (const float*)d_in[4];
    const float* Wv = (const float*)d_in[5];
    const float* bv = (const float*)d_in[6];
    const float* Wo = (const float*)d_in[7];
    const float* bo = (const float*)d_in[8];
    float* out = (float*)d_out;

    __half *p_xh, *p_kvh, *p_qh, *p_kh, *p_vh, *p_ctxh, *p_wq, *p_wk, *p_wv, *p_wo;
    cudaGetSymbolAddress((void**)&p_xh,   g_xh);
    cudaGetSymbolAddress((void**)&p_kvh,  g_kvh);
    cudaGetSymbolAddress((void**)&p_qh,   g_qh);
    cudaGetSymbolAddress((void**)&p_kh,   g_kh);
    cudaGetSymbolAddress((void**)&p_vh,   g_vh);
    cudaGetSymbolAddress((void**)&p_ctxh, g_ctxh);
    cudaGetSymbolAddress((void**)&p_wq,   g_wq);
    cudaGetSymbolAddress((void**)&p_wk,   g_wk);
    cudaGetSymbolAddress((void**)&p_wv,   g_wv);
    cudaGetSymbolAddress((void**)&p_wo,   g_wo);

    cudaFuncSetAttribute(gemm_h, cudaFuncAttributeMaxDynamicSharedMemorySize, GEMM_SMEM);

    cvt_f2h<<<(QROWS*DM/4)/256, 256>>>(x,  p_xh);
    cvt_f2h<<<(DM*DM/4)/256,    256>>>(Wq, p_wq);
    cvt_f2h<<<(DM*DM/4)/256,    256>>>(Wk, p_wk);
    cvt_f2h<<<(DM*DM/4)/256,    256>>>(Wv, p_wv);
    cvt_f2h<<<(DM*DM/4)/256,    256>>>(Wo, p_wo);
    landmark_kernel<<<BATCH*NLM, DM>>>(x);
    gather_kv_h<<<(KVROWS*192)/256, 256>>>(x);

    GArgs aq = { p_xh,   p_wq, bq, p_qh, nullptr, QROWS  };
    GArgs ak = { p_kvh,  p_wk, bk, p_kh, nullptr, KVROWS };
    GArgs av = { p_kvh,  p_wv, bv, p_vh, nullptr, KVROWS };
    gemm_h<<<dim3(6, KVROWS/128, 3), 256, GEMM_SMEM>>>(aq, ak, av);

    attn_kernel<<<dim3(4, NH, BATCH*NCH), 256>>>();

    GArgs ao = { p_ctxh, p_wo, bo, nullptr, out, QROWS };
    gemm_h<<<dim3(6, QROWS/128, 1), 256, GEMM_SMEM>>>(ao, ao, ao);
}